// round 2
// baseline (speedup 1.0000x reference)
#include <cuda_runtime.h>
#include <math.h>

#define NN 100000
#define EE 1600000
#define NCAND 10000
#define GG 1000
#define ND 32
#define ED 8
#define LL 4
#define NB_SCAN 98   // ceil(NN/1024)

// Scratch (static device globals — no runtime allocation)
__device__ float g_h[NN * ND];        // node embeddings       12.8 MB
__device__ float g_hs[NN * ED];       // h @ Ws + be            3.2 MB
__device__ float g_hd[NN * ED];       // h @ Wd                 3.2 MB
__device__ float g_e[EE * ED];        // edge embeddings (dst-sorted order) 51.2 MB
__device__ float g_ne[EE * ED];       // new_e per edge (dst-sorted)        51.2 MB
__device__ int   g_src_s[EE];         // src per sorted edge
__device__ int   g_dst_s[EE];         // dst per sorted edge
__device__ int   g_cnt[NN];           // histogram
__device__ int   g_off[NN + 1];       // CSR offsets by dst
__device__ int   g_run[NN];           // running offsets for scatter
__device__ int   g_bsum[NB_SCAN];
__device__ float g_logits[NCAND];
__device__ int   g_seg[NCAND];
__device__ float g_mx[GG];
__device__ float g_sum[GG];

// ---------------- counting sort by dst (once per call) ----------------

__global__ void k_zero_cnt() {
    int t = blockIdx.x * blockDim.x + threadIdx.x;
    if (t < NN) g_cnt[t] = 0;
}

__global__ void k_hist(const int* __restrict__ ei) {
    int e = blockIdx.x * blockDim.x + threadIdx.x;
    if (e < EE) atomicAdd(&g_cnt[ei[EE + e]], 1);
}

__global__ void k_scan1() {
    __shared__ int sd[1024];
    int g = blockIdx.x * 1024 + threadIdx.x;
    int v = (g < NN) ? g_cnt[g] : 0;
    sd[threadIdx.x] = v;
    __syncthreads();
    for (int off = 1; off < 1024; off <<= 1) {
        int t = (threadIdx.x >= off) ? sd[threadIdx.x - off] : 0;
        __syncthreads();
        sd[threadIdx.x] += t;
        __syncthreads();
    }
    if (g < NN) g_off[g] = sd[threadIdx.x] - v;  // exclusive within block
    if (threadIdx.x == 1023) g_bsum[blockIdx.x] = sd[1023];
}

__global__ void k_scan2() {
    // single thread exclusive scan of 98 block sums
    int run = 0;
    for (int i = 0; i < NB_SCAN; i++) {
        int t = g_bsum[i];
        g_bsum[i] = run;
        run += t;
    }
}

__global__ void k_scan3() {
    int t = blockIdx.x * blockDim.x + threadIdx.x;
    if (t < NN) {
        int v = g_off[t] + g_bsum[t >> 10];
        g_off[t] = v;
        g_run[t] = v;
    }
    if (t == 0) g_off[NN] = EE;
}

// scatter edges into dst-sorted order; fuse edge-embedding init
__global__ void k_scatter(const int* __restrict__ ei,
                          const float* __restrict__ ea,
                          const float* __restrict__ We,
                          const float* __restrict__ be) {
    int e = blockIdx.x * blockDim.x + threadIdx.x;
    if (e >= EE) return;
    int dst = ei[EE + e];
    int pos = atomicAdd(&g_run[dst], 1);
    g_src_s[pos] = ei[e];
    g_dst_s[pos] = dst;
    float v = ea[e];
    float4 a = make_float4(fmaf(v, We[0], be[0]), fmaf(v, We[1], be[1]),
                           fmaf(v, We[2], be[2]), fmaf(v, We[3], be[3]));
    float4 b = make_float4(fmaf(v, We[4], be[4]), fmaf(v, We[5], be[5]),
                           fmaf(v, We[6], be[6]), fmaf(v, We[7], be[7]));
    float4* ep = (float4*)&g_e[(size_t)pos * ED];
    ep[0] = a;
    ep[1] = b;
}

// ---------------- GNN layers ----------------

__global__ void k_init_h(const float* __restrict__ x,
                         const float* __restrict__ Wn,
                         const float* __restrict__ bn) {
    int t = blockIdx.x * blockDim.x + threadIdx.x;
    if (t >= NN * ND) return;
    int n = t >> 5, c = t & 31;
    g_h[t] = fmaf(x[2 * n], Wn[c], fmaf(x[2 * n + 1], Wn[ND + c], bn[c]));
}

// Per-node precompute: hs = h@Ws + be, hd = h@Wd
__global__ void k_pre(const float* __restrict__ Wel,
                      const float* __restrict__ bel, int l) {
    __shared__ float sW[2 * ND * ED];
    __shared__ float sb[ED];
    const float* W = Wel + l * (2 * ND + ED) * ED;
    for (int i = threadIdx.x; i < 2 * ND * ED; i += blockDim.x) sW[i] = W[i];
    if (threadIdx.x < ED) sb[threadIdx.x] = bel[l * ED + threadIdx.x];
    __syncthreads();
    int t = blockIdx.x * blockDim.x + threadIdx.x;
    if (t >= NN * ED) return;
    int n = t >> 3, j = t & 7;
    const float* hrow = &g_h[n * ND];
    float accs = sb[j], accd = 0.f;
#pragma unroll
    for (int i = 0; i < ND; i++) {
        float hv = hrow[i];
        accs = fmaf(hv, sW[i * ED + j], accs);
        accd = fmaf(hv, sW[(ND + i) * ED + j], accd);
    }
    g_hs[t] = accs;
    g_hd[t] = accd;
}

// Per-edge (dst-sorted): new_e = relu(hs[src]+hd[dst]+e@We); store ne; e += ne
__global__ void k_edge(const float* __restrict__ Wel, int l) {
    __shared__ float sW[ED * ED];
    if (threadIdx.x < ED * ED)
        sW[threadIdx.x] = Wel[l * (2 * ND + ED) * ED + 2 * ND * ED + threadIdx.x];
    __syncthreads();
    int e = blockIdx.x * blockDim.x + threadIdx.x;
    if (e >= EE) return;
    int src = g_src_s[e], dst = g_dst_s[e];
    const float4* ep = (const float4*)&g_e[(size_t)e * ED];
    float4 e0 = ep[0], e1 = ep[1];
    const float4* sp = (const float4*)&g_hs[(size_t)src * ED];
    float4 s0 = sp[0], s1 = sp[1];
    const float4* dp = (const float4*)&g_hd[(size_t)dst * ED];
    float4 d0 = dp[0], d1 = dp[1];
    float ein[8] = {e0.x, e0.y, e0.z, e0.w, e1.x, e1.y, e1.z, e1.w};
    float base[8] = {s0.x + d0.x, s0.y + d0.y, s0.z + d0.z, s0.w + d0.w,
                     s1.x + d1.x, s1.y + d1.y, s1.z + d1.z, s1.w + d1.w};
    float ne[8];
#pragma unroll
    for (int j = 0; j < 8; j++) {
        float acc = base[j];
#pragma unroll
        for (int i = 0; i < 8; i++) acc = fmaf(ein[i], sW[i * ED + j], acc);
        ne[j] = fmaxf(acc, 0.f);
    }
    float4* np = (float4*)&g_ne[(size_t)e * ED];
    np[0] = make_float4(ne[0], ne[1], ne[2], ne[3]);
    np[1] = make_float4(ne[4], ne[5], ne[6], ne[7]);
    float4* eo = (float4*)&g_e[(size_t)e * ED];
    eo[0] = make_float4(ein[0] + ne[0], ein[1] + ne[1], ein[2] + ne[2], ein[3] + ne[3]);
    eo[1] = make_float4(ein[4] + ne[4], ein[5] + ne[5], ein[6] + ne[6], ein[7] + ne[7]);
}

// Warp per node: segmented sum of ne over incoming edges + node MLP + residual
__global__ void k_node(const float* __restrict__ Wnl,
                       const float* __restrict__ bnl, int l) {
    __shared__ float sW[(ND + ED) * ND];
    __shared__ float sb[ND];
    for (int i = threadIdx.x; i < (ND + ED) * ND; i += blockDim.x)
        sW[i] = Wnl[l * (ND + ED) * ND + i];
    if (threadIdx.x < ND) sb[threadIdx.x] = bnl[l * ND + threadIdx.x];
    __syncthreads();
    int warp = (blockIdx.x * blockDim.x + threadIdx.x) >> 5;
    int lane = threadIdx.x & 31;
    if (warp >= NN) return;
    int beg = g_off[warp], end = g_off[warp + 1];
    int sub = lane >> 3, col = lane & 7;
    float acc = 0.f;
    for (int t = beg + sub; t < end; t += 4)
        acc += g_ne[(size_t)t * ED + col];
    acc += __shfl_down_sync(0xffffffffu, acc, 16);
    acc += __shfl_down_sync(0xffffffffu, acc, 8);
    float av = acc;  // lanes 0..7 hold agg columns 0..7
    float hv = g_h[warp * ND + lane];
    float r = sb[lane];
#pragma unroll
    for (int i = 0; i < ND; i++)
        r = fmaf(__shfl_sync(0xffffffffu, hv, i), sW[i * ND + lane], r);
#pragma unroll
    for (int i = 0; i < ED; i++)
        r = fmaf(__shfl_sync(0xffffffffu, av, i), sW[(ND + i) * ND + lane], r);
    g_h[warp * ND + lane] = hv + fmaxf(r, 0.f);
}

// ---------------- readout ----------------

__global__ void k_finit() {
    int t = blockIdx.x * blockDim.x + threadIdx.x;
    if (t < GG) { g_mx[t] = -INFINITY; g_sum[t] = 0.f; }
}

__global__ void k_logits(const int* __restrict__ cand,
                         const int* __restrict__ batch,
                         const float* __restrict__ Wout,
                         const float* __restrict__ bout) {
    int c = blockIdx.x * blockDim.x + threadIdx.x;
    if (c >= NCAND) return;
    int n = cand[c];
    float acc = bout[0];
    const float* hrow = &g_h[n * ND];
#pragma unroll
    for (int i = 0; i < ND; i++) acc = fmaf(hrow[i], Wout[i], acc);
    g_logits[c] = acc;
    int s = batch[n];
    g_seg[c] = s;
    if (acc >= 0.f) atomicMax((int*)&g_mx[s], __float_as_int(acc));
    else            atomicMin((unsigned int*)&g_mx[s], __float_as_uint(acc));
}

__global__ void k_sumexp() {
    int c = blockIdx.x * blockDim.x + threadIdx.x;
    if (c >= NCAND) return;
    int s = g_seg[c];
    float sh = g_logits[c] - g_mx[s];
    g_logits[c] = sh;
    atomicAdd(&g_sum[s], expf(sh));
}

__global__ void k_out(float* __restrict__ out) {
    int c = blockIdx.x * blockDim.x + threadIdx.x;
    if (c >= NCAND) return;
    out[c] = g_logits[c] - logf(g_sum[g_seg[c]]);
}

extern "C" void kernel_launch(void* const* d_in, const int* in_sizes, int n_in,
                              void* d_out, int out_size) {
    const float* x         = (const float*)d_in[0];
    const float* edge_attr = (const float*)d_in[1];
    const float* Wn_in     = (const float*)d_in[2];
    const float* bn_in     = (const float*)d_in[3];
    const float* We_in     = (const float*)d_in[4];
    const float* be_in     = (const float*)d_in[5];
    const float* We_l      = (const float*)d_in[6];
    const float* be_l      = (const float*)d_in[7];
    const float* Wn_l      = (const float*)d_in[8];
    const float* bn_l      = (const float*)d_in[9];
    const float* Wout      = (const float*)d_in[10];
    const float* bout      = (const float*)d_in[11];
    const int* edge_index  = (const int*)d_in[12];
    const int* batch       = (const int*)d_in[13];
    const int* cand        = (const int*)d_in[14];
    float* out = (float*)d_out;

    // counting sort of edges by dst + fused edge-embedding init
    k_zero_cnt<<<(NN + 255) / 256, 256>>>();
    k_hist<<<(EE + 255) / 256, 256>>>(edge_index);
    k_scan1<<<NB_SCAN, 1024>>>();
    k_scan2<<<1, 1>>>();
    k_scan3<<<(NN + 255) / 256, 256>>>();
    k_scatter<<<(EE + 255) / 256, 256>>>(edge_index, edge_attr, We_in, be_in);

    k_init_h<<<(NN * ND + 255) / 256, 256>>>(x, Wn_in, bn_in);
    for (int l = 0; l < LL; l++) {
        k_pre<<<(NN * ED + 255) / 256, 256>>>(We_l, be_l, l);
        k_edge<<<(EE + 255) / 256, 256>>>(We_l, l);
        k_node<<<(NN * 32 + 255) / 256, 256>>>(Wn_l, bn_l, l);
    }
    k_finit<<<(GG + 255) / 256, 256>>>();
    k_logits<<<(NCAND + 255) / 256, 256>>>(cand, batch, Wout, bout);
    k_sumexp<<<(NCAND + 255) / 256, 256>>>();
    k_out<<<(NCAND + 255) / 256, 256>>>(out);
}

// round 3
// speedup vs baseline: 1.3208x; 1.3208x over previous
#include <cuda_runtime.h>
#include <cuda_fp16.h>
#include <math.h>

#define NN 100000
#define EE 1600000
#define NCAND 10000
#define GG 1000
#define ND 32
#define ED 8
#define LL 4

// Scratch (static device globals — no runtime allocation)
__device__ float g_h[NN * ND];                       // 12.8 MB fp32
__device__ __align__(16) __half g_hs[NN * ED];       // 1.6 MB fp16
__device__ __align__(16) __half g_hd[NN * ED];       // 1.6 MB fp16
__device__ __align__(16) float  g_agg[NN * ED];      // 3.2 MB fp32
__device__ __align__(16) __half g_e[(size_t)EE * ED];// 25.6 MB fp16
__device__ float g_logits[NCAND];
__device__ int   g_seg[NCAND];
__device__ float g_mx[GG];
__device__ float g_sum[GG];

#define R_A (NN * ND)              // h init
#define R_B (R_A + NN * 16)        // hs/hd layer 0
#define R_C (R_B + EE)             // e init
#define R_D (R_C + NN * ED)        // agg zero
#define R_E (R_D + GG)             // softmax state init
#define TOT R_E

// One fused init kernel: h, layer-0 hs/hd (via folded 2x16 matrix), e (fp16),
// agg zero, per-graph max/sum init.
__global__ void k_init(const float* __restrict__ x,
                       const float* __restrict__ Wn,   // Wn_in [2,32]
                       const float* __restrict__ bn,   // bn_in [32]
                       const float* __restrict__ ea,
                       const float* __restrict__ Wei,  // We_in [1,8]
                       const float* __restrict__ bei,  // be_in [8]
                       const float* __restrict__ Wel,  // We_l
                       const float* __restrict__ bel)  // be_l
{
    // Fold: hs0 = x @ (Wn_in @ Ws0) + (bn_in @ Ws0 + be0); same for hd0.
    __shared__ float sC[2][16];
    __shared__ float sc0[16];
    int tid = threadIdx.x;
    if (tid < 48) {
        int r = tid >> 4;     // 0,1 -> C rows; 2 -> c0
        int j = tid & 15;
        float acc = 0.f;
        if (r < 2) {
            for (int i = 0; i < ND; i++) {
                float w = (j < 8) ? Wel[i * ED + j] : Wel[(ND + i) * ED + (j - 8)];
                acc = fmaf(Wn[r * ND + i], w, acc);
            }
            sC[r][j] = acc;
        } else {
            for (int i = 0; i < ND; i++) {
                float w = (j < 8) ? Wel[i * ED + j] : Wel[(ND + i) * ED + (j - 8)];
                acc = fmaf(bn[i], w, acc);
            }
            sc0[j] = acc + ((j < 8) ? bel[j] : 0.f);
        }
    }
    __syncthreads();
    long t = (long)blockIdx.x * blockDim.x + tid;
    if (t < R_A) {
        int n = (int)(t >> 5), c = (int)(t & 31);
        g_h[t] = fmaf(x[2 * n], Wn[c], fmaf(x[2 * n + 1], Wn[ND + c], bn[c]));
    } else if (t < R_B) {
        long u = t - R_A;
        int n = (int)(u >> 4), j = (int)(u & 15);
        float v = fmaf(x[2 * n], sC[0][j], fmaf(x[2 * n + 1], sC[1][j], sc0[j]));
        if (j < 8) g_hs[n * ED + j] = __float2half(v);
        else       g_hd[n * ED + (j - 8)] = __float2half(v);
    } else if (t < R_C) {
        long e = t - R_B;
        float v = ea[e];
        __half2 h4[4];
#pragma unroll
        for (int k = 0; k < 4; k++) {
            float a = fmaf(v, Wei[2 * k], bei[2 * k]);
            float b = fmaf(v, Wei[2 * k + 1], bei[2 * k + 1]);
            h4[k] = __floats2half2_rn(a, b);
        }
        ((uint4*)g_e)[e] = *(uint4*)h4;
    } else if (t < R_D) {
        g_agg[t - R_C] = 0.f;
    } else if (t < R_E) {
        int g = (int)(t - R_D);
        g_mx[g] = -INFINITY;
        g_sum[g] = 0.f;
    }
}

// Per-edge: new_e = relu(hs[src]+hd[dst]+e@We), agg[dst]+=new_e (atomic), e+=new_e
__global__ void k_edge(const int* __restrict__ ei,
                       const float* __restrict__ Wel, int l) {
    __shared__ float sW[ED * ED];
    if (threadIdx.x < ED * ED)
        sW[threadIdx.x] = Wel[l * (2 * ND + ED) * ED + 2 * ND * ED + threadIdx.x];
    __syncthreads();
    int e = blockIdx.x * blockDim.x + threadIdx.x;
    if (e >= EE) return;
    int src = ei[e], dst = ei[EE + e];
    uint4 ev = ((const uint4*)g_e)[e];
    uint4 sv = *(const uint4*)&g_hs[src * ED];
    uint4 dv = *(const uint4*)&g_hd[dst * ED];
    const __half2* eh = (const __half2*)&ev;
    const __half2* sh = (const __half2*)&sv;
    const __half2* dh = (const __half2*)&dv;
    float ein[8], base[8];
#pragma unroll
    for (int k = 0; k < 4; k++) {
        float2 ef = __half22float2(eh[k]);
        float2 sf = __half22float2(sh[k]);
        float2 df = __half22float2(dh[k]);
        ein[2 * k] = ef.x;      ein[2 * k + 1] = ef.y;
        base[2 * k] = sf.x + df.x;
        base[2 * k + 1] = sf.y + df.y;
    }
    float ne[8];
#pragma unroll
    for (int j = 0; j < 8; j++) {
        float acc = base[j];
#pragma unroll
        for (int i = 0; i < 8; i++) acc = fmaf(ein[i], sW[i * ED + j], acc);
        ne[j] = fmaxf(acc, 0.f);
    }
    float* ap = &g_agg[(size_t)dst * ED];
    asm volatile("red.global.add.v4.f32 [%0], {%1,%2,%3,%4};"
                 :: "l"(ap), "f"(ne[0]), "f"(ne[1]), "f"(ne[2]), "f"(ne[3]) : "memory");
    asm volatile("red.global.add.v4.f32 [%0], {%1,%2,%3,%4};"
                 :: "l"(ap + 4), "f"(ne[4]), "f"(ne[5]), "f"(ne[6]), "f"(ne[7]) : "memory");
    __half2 out[4];
#pragma unroll
    for (int k = 0; k < 4; k++)
        out[k] = __floats2half2_rn(ein[2 * k] + ne[2 * k], ein[2 * k + 1] + ne[2 * k + 1]);
    ((uint4*)g_e)[e] = *(uint4*)out;
}

// Warp per node: node MLP + residual; epilogue computes NEXT layer's hs/hd
// (fp16) and re-zeros agg — eliminates the separate k_pre kernel.
__global__ void k_node(const float* __restrict__ Wnl,
                       const float* __restrict__ bnl,
                       const float* __restrict__ Wel,
                       const float* __restrict__ bel, int l) {
    __shared__ float sW[(ND + ED) * ND];
    __shared__ float sb[ND];
    __shared__ float sE[ND][16];
    __shared__ float sbe[8];
    const int last = (l == LL - 1);
    for (int i = threadIdx.x; i < (ND + ED) * ND; i += blockDim.x)
        sW[i] = Wnl[l * (ND + ED) * ND + i];
    if (threadIdx.x < ND) sb[threadIdx.x] = bnl[l * ND + threadIdx.x];
    if (!last) {
        const float* W = Wel + (l + 1) * (2 * ND + ED) * ED;
        for (int i = threadIdx.x; i < ND * 16; i += blockDim.x) {
            int r = i >> 4, j = i & 15;
            sE[r][j] = (j < 8) ? W[r * ED + j] : W[(ND + r) * ED + (j - 8)];
        }
        if (threadIdx.x < 8) sbe[threadIdx.x] = bel[(l + 1) * ED + threadIdx.x];
    }
    __syncthreads();
    int warp = (blockIdx.x * blockDim.x + threadIdx.x) >> 5;
    int lane = threadIdx.x & 31;
    if (warp >= NN) return;
    float hv = g_h[warp * ND + lane];
    float av = (lane < ED) ? g_agg[warp * ED + lane] : 0.f;
    float r = sb[lane];
#pragma unroll
    for (int i = 0; i < ND; i++)
        r = fmaf(__shfl_sync(0xffffffffu, hv, i), sW[i * ND + lane], r);
#pragma unroll
    for (int i = 0; i < ED; i++)
        r = fmaf(__shfl_sync(0xffffffffu, av, i), sW[(ND + i) * ND + lane], r);
    float hnew = hv + fmaxf(r, 0.f);
    g_h[warp * ND + lane] = hnew;
    if (!last) {
        float acc = (lane < 8) ? sbe[lane] : 0.f;
        int jj = lane & 15;
#pragma unroll
        for (int i = 0; i < ND; i++)
            acc = fmaf(__shfl_sync(0xffffffffu, hnew, i), sE[i][jj], acc);
        if (lane < 8) {
            g_hs[warp * ED + lane] = __float2half(acc);
            g_agg[warp * ED + lane] = 0.f;
        } else if (lane < 16) {
            g_hd[warp * ED + (lane - 8)] = __float2half(acc);
        }
    }
}

// ---------------- readout ----------------

__global__ void k_logits(const int* __restrict__ cand,
                         const int* __restrict__ batch,
                         const float* __restrict__ Wout,
                         const float* __restrict__ bout) {
    int c = blockIdx.x * blockDim.x + threadIdx.x;
    if (c >= NCAND) return;
    int n = cand[c];
    float acc = bout[0];
    const float* hrow = &g_h[n * ND];
#pragma unroll
    for (int i = 0; i < ND; i++) acc = fmaf(hrow[i], Wout[i], acc);
    g_logits[c] = acc;
    int s = batch[n];
    g_seg[c] = s;
    if (acc >= 0.f) atomicMax((int*)&g_mx[s], __float_as_int(acc));
    else            atomicMin((unsigned int*)&g_mx[s], __float_as_uint(acc));
}

__global__ void k_sumexp() {
    int c = blockIdx.x * blockDim.x + threadIdx.x;
    if (c >= NCAND) return;
    int s = g_seg[c];
    float sh = g_logits[c] - g_mx[s];
    g_logits[c] = sh;
    atomicAdd(&g_sum[s], expf(sh));
}

__global__ void k_out(float* __restrict__ out) {
    int c = blockIdx.x * blockDim.x + threadIdx.x;
    if (c >= NCAND) return;
    out[c] = g_logits[c] - logf(g_sum[g_seg[c]]);
}

extern "C" void kernel_launch(void* const* d_in, const int* in_sizes, int n_in,
                              void* d_out, int out_size) {
    const float* x         = (const float*)d_in[0];
    const float* edge_attr = (const float*)d_in[1];
    const float* Wn_in     = (const float*)d_in[2];
    const float* bn_in     = (const float*)d_in[3];
    const float* We_in     = (const float*)d_in[4];
    const float* be_in     = (const float*)d_in[5];
    const float* We_l      = (const float*)d_in[6];
    const float* be_l      = (const float*)d_in[7];
    const float* Wn_l      = (const float*)d_in[8];
    const float* bn_l      = (const float*)d_in[9];
    const float* Wout      = (const float*)d_in[10];
    const float* bout      = (const float*)d_in[11];
    const int* edge_index  = (const int*)d_in[12];
    const int* batch       = (const int*)d_in[13];
    const int* cand        = (const int*)d_in[14];
    float* out = (float*)d_out;

    k_init<<<(TOT + 255) / 256, 256>>>(x, Wn_in, bn_in, edge_attr, We_in, be_in,
                                       We_l, be_l);
    for (int l = 0; l < LL; l++) {
        k_edge<<<(EE + 255) / 256, 256>>>(edge_index, We_l, l);
        k_node<<<(NN * 32 + 255) / 256, 256>>>(Wn_l, bn_l, We_l, be_l, l);
    }
    k_logits<<<(NCAND + 255) / 256, 256>>>(cand, batch, Wout, bout);
    k_sumexp<<<(NCAND + 255) / 256, 256>>>();
    k_out<<<(NCAND + 255) / 256, 256>>>(out);
}